// round 2
// baseline (speedup 1.0000x reference)
#include <cuda_runtime.h>
#include <cstdint>

// KV cache update:
//   kv_cache: (2L, B, H, S, D) fp32, L=2,B=8,H=8,S=4096,D=128
//   new_kv:   (L, 2, B, H, 1, D) fp32
//   position_ids: (B, 1)  -- int64 in source, but may be serialized as int32
// out = kv_cache with out[2l+kv, b, h, pos[b], :] = new_kv[l, kv, b, h, 0, :]
//
// Strategy: 512 MiB D2D memcpy (CE) + tiny scatter kernel (256 rows x 128 floats).

static constexpr unsigned Bv  = 8;
static constexpr unsigned Hv  = 8;
static constexpr unsigned Sv  = 4096;
static constexpr unsigned D4  = 128 / 4;                 // float4 per row
static constexpr unsigned NROWS = 4 * Bv * Hv;           // 2L * B * H = 256
static constexpr unsigned NSC   = NROWS * D4;            // 8192 float4 scatter writes
static constexpr size_t   CACHE_BYTES = (size_t)4 * Bv * Hv * Sv * 128 * sizeof(float);

// Robustly fetch pos[b] whether the buffer is int32[8] or int64[8] (LE).
__device__ __forceinline__ int load_pos(const int* __restrict__ pw, unsigned b)
{
    bool is64 = true;
#pragma unroll
    for (int i = 0; i < 8; ++i)
        is64 &= (pw[2 * i + 1] == 0);
    // int64 LE: low word of element b is pw[2b]; int32: pw[b]
    return is64 ? pw[2 * b] : pw[b];
}

__global__ void __launch_bounds__(256)
kv_scatter_kernel(const float4* __restrict__ newkv,
                  const int*    __restrict__ posw,
                  float4*       __restrict__ out)
{
    unsigned idx = blockIdx.x * 256u + threadIdx.x;      // < 8192
    if (idx >= NSC) return;

    // new_kv linear layout: [lkv][b][h][d4]  (lkv = 2*l + kv matches output order)
    unsigned d4  = idx & 31u;
    unsigned h   = (idx >> 5) & 7u;
    unsigned b   = (idx >> 8) & 7u;
    unsigned lkv = idx >> 11;                            // 0..3

    int p = load_pos(posw, b);

    // out layout: [lkv][b][h][s][d4], strides lkv=2^23, b=2^20, h=2^17, s=32
    size_t oidx = ((size_t)lkv << 23) | ((size_t)b << 20) | ((size_t)h << 17)
                | ((size_t)(unsigned)p << 5) | d4;

    out[oidx] = newkv[idx];
}

extern "C" void kernel_launch(void* const* d_in, const int* in_sizes, int n_in,
                              void* d_out, int out_size)
{
    const float4* cache = (const float4*)d_in[0];
    const float4* newkv = (const float4*)d_in[1];
    const int*    posw  = (const int*)d_in[2];
    float4*       out   = (float4*)d_out;

    // Bulk copy via copy engine (graph-capturable memcpy node).
    cudaMemcpyAsync(out, cache, CACHE_BYTES, cudaMemcpyDeviceToDevice, 0);

    // Overwrite the 256 updated rows.
    kv_scatter_kernel<<<NSC / 256, 256>>>(newkv, posw, out);
}

// round 3
// speedup vs baseline: 2.1686x; 2.1686x over previous
#include <cuda_runtime.h>
#include <cstdint>

// KV cache update:
//   kv_cache: (2L, B, H, S, D) fp32, L=2,B=8,H=8,S=4096,D=128
//   new_kv:   (L, 2, B, H, 1, D) fp32
//   position_ids: (B, 1)  -- int64 in source, possibly serialized as int32
// out = kv_cache with out[2l+kv, b, h, pos[b], :] = new_kv[l, kv, b, h, 0, :]
//
// Strategy: SM-driven streaming copy (CE memcpy only hit ~3.1 TB/s; SMs can
// saturate the ~6.3 TB/s LTS/HBM path) + tiny scatter kernel for 256 rows.

static constexpr unsigned Bv  = 8;
static constexpr unsigned Hv  = 8;
static constexpr unsigned Sv  = 4096;
static constexpr unsigned D4  = 128 / 4;                 // float4 per row
static constexpr unsigned NROWS = 4 * Bv * Hv;           // 2L*B*H = 256
static constexpr unsigned NSC   = NROWS * D4;            // 8192 scatter float4s
static constexpr unsigned N4    = 4u * Bv * Hv * Sv * D4;  // 2^25 float4 total

// ---------------- bulk copy: 4 x float4 per thread (64B), MLP=4 ----------------
static constexpr unsigned VPT   = 4;                     // float4 per thread
static constexpr unsigned TPB   = 256;
static constexpr unsigned NBLK  = N4 / (VPT * TPB);      // 2^25 / 1024 = 32768

__global__ void __launch_bounds__(TPB)
kv_copy_kernel(const float4* __restrict__ src, float4* __restrict__ dst)
{
    // Coalesced: block covers a contiguous span of VPT*TPB float4s,
    // thread t handles elements {base + t, base + t + TPB, ...}.
    unsigned base = blockIdx.x * (VPT * TPB) + threadIdx.x;

    float4 v0 = src[base + 0 * TPB];
    float4 v1 = src[base + 1 * TPB];
    float4 v2 = src[base + 2 * TPB];
    float4 v3 = src[base + 3 * TPB];

    dst[base + 0 * TPB] = v0;
    dst[base + 1 * TPB] = v1;
    dst[base + 2 * TPB] = v2;
    dst[base + 3 * TPB] = v3;
}

// ---------------- scatter: overwrite the 256 updated rows ----------------
// Robustly fetch pos[b] whether the buffer is int32[8] or int64[8] (LE).
// Positions are in [0, 4096) so int64 high words are all zero; for int32 data
// the odd words are random positions (P(all zero) ~ 4096^-4, negligible).
__device__ __forceinline__ int load_pos(const int* __restrict__ pw, unsigned b)
{
    bool is64 = true;
#pragma unroll
    for (int i = 0; i < 8; ++i)
        is64 &= (pw[2 * i + 1] == 0);
    return is64 ? pw[2 * b] : pw[b];
}

__global__ void __launch_bounds__(256)
kv_scatter_kernel(const float4* __restrict__ newkv,
                  const int*    __restrict__ posw,
                  float4*       __restrict__ out)
{
    unsigned idx = blockIdx.x * 256u + threadIdx.x;      // < 8192

    // new_kv linear layout: [lkv][b][h][d4]  (lkv = 2*l + kv matches output order)
    unsigned d4  = idx & 31u;
    unsigned h   = (idx >> 5) & 7u;
    unsigned b   = (idx >> 8) & 7u;
    unsigned lkv = idx >> 11;                            // 0..3

    int p = load_pos(posw, b);

    // out layout: [lkv][b][h][s][d4], strides lkv=2^23, b=2^20, h=2^17, s=32
    size_t oidx = ((size_t)lkv << 23) | ((size_t)b << 20) | ((size_t)h << 17)
                | ((size_t)(unsigned)p << 5) | d4;

    out[oidx] = newkv[idx];
}

extern "C" void kernel_launch(void* const* d_in, const int* in_sizes, int n_in,
                              void* d_out, int out_size)
{
    const float4* cache = (const float4*)d_in[0];
    const float4* newkv = (const float4*)d_in[1];
    const int*    posw  = (const int*)d_in[2];
    float4*       out   = (float4*)d_out;

    kv_copy_kernel<<<NBLK, TPB>>>(cache, out);
    kv_scatter_kernel<<<NSC / 256, 256>>>(newkv, posw, out);
}

// round 4
// speedup vs baseline: 2.1897x; 1.0097x over previous
#include <cuda_runtime.h>
#include <cstdint>

// KV cache update:
//   kv_cache: (2L, B, H, S, D) fp32, L=2,B=8,H=8,S=4096,D=128
//   new_kv:   (L, 2, B, H, 1, D) fp32
//   position_ids: (B, 1)  -- int64 in source, possibly serialized as int32
// out = kv_cache with out[2l+kv, b, h, pos[b], :] = new_kv[l, kv, b, h, 0, :]
//
// Single fused streaming kernel: copy 512 MiB with predicated overwrite of the
// 256 updated rows. SM-driven (CE memcpy only ~3.1 TB/s; this path ~7 TB/s).
// Evict-first cache hints since every byte is touched exactly once.

static constexpr unsigned Bv  = 8;
static constexpr unsigned Hv  = 8;
static constexpr unsigned Sv  = 4096;
static constexpr unsigned D4  = 128 / 4;                   // float4 per row
static constexpr unsigned N4  = 4u * Bv * Hv * Sv * D4;    // 2^25 float4 total

static constexpr unsigned VPT  = 4;                        // float4 per thread
static constexpr unsigned TPB  = 256;
static constexpr unsigned NBLK = N4 / (VPT * TPB);         // 32768

// Robustly fetch pos[b] whether the buffer is int32[8] or int64[8] (LE).
// Positions are in [0, 4096) so int64 high words are all zero; for int32 data
// the odd words are random positions (P(all zero) ~ 4096^-4, negligible).
__device__ __forceinline__ int load_pos(const int* __restrict__ pw, unsigned b)
{
    bool is64 = true;
#pragma unroll
    for (int i = 0; i < 8; ++i)
        is64 &= (pw[2 * i + 1] == 0);
    return is64 ? pw[2 * b] : pw[b];
}

__global__ void __launch_bounds__(TPB)
kv_fused_kernel(const float4* __restrict__ src,
                const float4* __restrict__ newkv,
                const int*    __restrict__ posw,
                float4*       __restrict__ dst)
{
    // Block covers a contiguous span of VPT*TPB = 1024 float4s = 32 rows.
    // Layout [lkv][b][h][s][d4]: lkv/b/h (bits >= 17) are block-constant.
    unsigned base = blockIdx.x * (VPT * TPB) + threadIdx.x;

    unsigned lkv = base >> 23;
    unsigned b   = (base >> 20) & 7u;
    unsigned h   = (base >> 17) & 7u;

    int p = load_pos(posw, b);                              // L1-resident
    unsigned rowbase = ((lkv * 8u + b) * 8u + h) * 32u;     // new_kv row offset

#pragma unroll
    for (unsigned j = 0; j < VPT; ++j) {
        unsigned idx = base + j * TPB;
        float4 v = __ldcs(&src[idx]);                       // evict-first read
        unsigned s = (idx >> 5) & 4095u;
        if ((int)s == p)
            v = newkv[rowbase + (idx & 31u)];
        __stcs(&dst[idx], v);                               // evict-first write
    }
}

extern "C" void kernel_launch(void* const* d_in, const int* in_sizes, int n_in,
                              void* d_out, int out_size)
{
    const float4* cache = (const float4*)d_in[0];
    const float4* newkv = (const float4*)d_in[1];
    const int*    posw  = (const int*)d_in[2];
    float4*       out   = (float4*)d_out;

    kv_fused_kernel<<<NBLK, TPB>>>(cache, newkv, posw, out);
}

// round 5
// speedup vs baseline: 2.2143x; 1.0113x over previous
#include <cuda_runtime.h>
#include <cstdint>

// KV cache update:
//   kv_cache: (2L, B, H, S, D) fp32, L=2,B=8,H=8,S=4096,D=128
//   new_kv:   (L, 2, B, H, 1, D) fp32
//   position_ids: (B, 1)  -- int64 in source, possibly serialized as int32
// out = kv_cache with out[2l+kv, b, h, pos[b], :] = new_kv[l, kv, b, h, 0, :]
//
// Single fused streaming kernel (memory-roofline bound: 1 GiB mandatory traffic).
// 8 x float4 per thread, loads front-batched for MLP=8, evict-first hints.

static constexpr unsigned Bv  = 8;
static constexpr unsigned Hv  = 8;
static constexpr unsigned Sv  = 4096;
static constexpr unsigned D4  = 128 / 4;                   // float4 per row
static constexpr unsigned N4  = 4u * Bv * Hv * Sv * D4;    // 2^25 float4 total

static constexpr unsigned VPT  = 8;                        // float4 per thread (128 B)
static constexpr unsigned TPB  = 256;
static constexpr unsigned NBLK = N4 / (VPT * TPB);         // 16384

// Robustly fetch pos[b] whether the buffer is int32[8] or int64[8] (LE).
// Positions are in [0, 4096) so int64 high words are all zero; for int32 data
// the odd words are random positions (P(all zero) ~ 4096^-4, negligible).
__device__ __forceinline__ int load_pos(const int* __restrict__ pw, unsigned b)
{
    bool is64 = true;
#pragma unroll
    for (int i = 0; i < 8; ++i)
        is64 &= (pw[2 * i + 1] == 0);
    return is64 ? pw[2 * b] : pw[b];
}

__global__ void __launch_bounds__(TPB)
kv_fused_kernel(const float4* __restrict__ src,
                const float4* __restrict__ newkv,
                const int*    __restrict__ posw,
                float4*       __restrict__ dst)
{
    // Block covers a contiguous span of VPT*TPB = 2048 float4s = 64 rows.
    // Layout [lkv][b][h][s][d4]: lkv/b/h (bits >= 17) are block-constant.
    unsigned base = blockIdx.x * (VPT * TPB) + threadIdx.x;

    unsigned lkv = base >> 23;
    unsigned b   = (base >> 20) & 7u;
    unsigned h   = (base >> 17) & 7u;

    int p = load_pos(posw, b);                              // L1-resident
    unsigned rowbase = ((lkv * 8u + b) * 8u + h) * 32u;     // new_kv row offset

    float4 v[VPT];
#pragma unroll
    for (unsigned j = 0; j < VPT; ++j)                      // front-batched: MLP=8
        v[j] = __ldcs(&src[base + j * TPB]);

#pragma unroll
    for (unsigned j = 0; j < VPT; ++j) {
        unsigned idx = base + j * TPB;
        unsigned s = (idx >> 5) & 4095u;
        if ((int)s == p)
            v[j] = newkv[rowbase + (idx & 31u)];
        __stcs(&dst[idx], v[j]);
    }
}

extern "C" void kernel_launch(void* const* d_in, const int* in_sizes, int n_in,
                              void* d_out, int out_size)
{
    const float4* cache = (const float4*)d_in[0];
    const float4* newkv = (const float4*)d_in[1];
    const int*    posw  = (const int*)d_in[2];
    float4*       out   = (float4*)d_out;

    kv_fused_kernel<<<NBLK, TPB>>>(cache, newkv, posw, out);
}